// round 1
// baseline (speedup 1.0000x reference)
#include <cuda_runtime.h>

#define NN 2000
#define EE 32000
#define BB 8
#define TT 12
#define CIN 32
#define FCH 64
#define TBm 96        // T*B flattened "batch" dim
#define ROWLEN 3072   // TBm*CIN floats per node

// ---------------- scratch (static device globals; no allocation) ----------------
__device__ float g_x0[NN*ROWLEN];
__device__ float g_y1[NN*ROWLEN];
__device__ float g_z2[NN*ROWLEN];
__device__ float g_out[NN*TBm*FCH];
__device__ float g_deg[NN];
__device__ int   g_cnt[NN];
__device__ int   g_rowptr[NN+1];
__device__ int   g_cursor[NN];
__device__ float g_selfw[NN];
__device__ int   g_col[EE];
__device__ float g_wval[EE];

// ---------------- CSR build ----------------
__global__ void k_zero() {
    int i = blockIdx.x*blockDim.x + threadIdx.x;
    if (i < NN) { g_cnt[i] = 0; g_deg[i] = 0.f; }
}

__global__ void k_count(const int* __restrict__ ei, const float* __restrict__ ew) {
    int e = blockIdx.x*blockDim.x + threadIdx.x;
    if (e < EE) {
        atomicAdd(&g_cnt[ei[EE + e]], 1);       // in-degree count over dst
        atomicAdd(&g_deg[ei[e]], ew[e]);        // weighted degree over src (PyG)
    }
}

__global__ void k_scan(const float* __restrict__ lmax) {
    __shared__ int sa[2048], sb[2048];
    int tid = threadIdx.x;
    for (int i = tid; i < 2048; i += 1024) sa[i] = (i < NN) ? g_cnt[i] : 0;
    __syncthreads();
    int* src = sa; int* dst = sb;
    for (int off = 1; off < 2048; off <<= 1) {
        for (int i = tid; i < 2048; i += 1024)
            dst[i] = src[i] + ((i >= off) ? src[i - off] : 0);
        __syncthreads();
        int* tp = src; src = dst; dst = tp;
    }
    float alpha = 2.0f / lmax[0];
    for (int i = tid; i < NN; i += 1024) {
        g_rowptr[i+1] = src[i];
        g_cursor[i]   = (i == 0) ? 0 : src[i-1];
        g_selfw[i]    = alpha * g_deg[i] - 1.0f;   // appended self-loop: 2*deg/lmax - 1
    }
    if (tid == 0) g_rowptr[0] = 0;
}

__global__ void k_scatter(const int* __restrict__ ei, const float* __restrict__ ew,
                          const float* __restrict__ lmax) {
    int e = blockIdx.x*blockDim.x + threadIdx.x;
    if (e < EE) {
        int s = ei[e], d = ei[EE + e];
        int pos = atomicAdd(&g_cursor[d], 1);
        float alpha = 2.0f / lmax[0];
        g_col[pos]  = s;
        // edge weight: 2*(-w)/lmax, and the (srcs==dsts) -1 applies to raw self-edges too
        g_wval[pos] = -alpha * ew[e] - ((s == d) ? 1.0f : 0.0f);
    }
}

// ---------------- x0 materialization (faithful buggy permute+reshape) ----------------
// Xt.flat == X_perm.flat where X_perm = X.transpose(2,0,1,3) (shape C,B,N,T).
// x0[n, m, c] = Xt[n, c, m]  with flat u = n*3072 + c*96 + m decomposed in (C,B,N,T).
__global__ void k_x0(const float* __restrict__ X) {
    __shared__ float s[32*97];   // padded: avoid 32-way conflicts on transpose
    int n2 = blockIdx.x;
    int tid = threadIdx.x;
    for (int i = tid; i < ROWLEN; i += 256) {
        int u = n2*ROWLEN + i;
        int c   = u / 192000;       int rem  = u - c*192000;
        int b   = rem / 24000;      int rem2 = rem - b*24000;
        int n   = rem2 / 12;        int t    = rem2 - n*12;
        int c2 = i / 96, m = i - c2*96;
        s[c2*97 + m] = X[((b*NN + n)*CIN + c)*TT + t];
    }
    __syncthreads();
    for (int i = tid; i < ROWLEN; i += 256) {
        int m = i >> 5, c2 = i & 31;
        g_x0[n2*ROWLEN + i] = s[c2*97 + m];
    }
}

// ---------------- graph propagation (CSR gather, no atomics) ----------------
// mode 1: y1 = L_hat x0 ; mode 2: z2 = 2*(L_hat y1) - x0
__global__ void k_prop(int mode) {
    const float* in  = (mode == 1) ? g_x0 : g_y1;
    float*       out = (mode == 1) ? g_y1 : g_z2;
    int n = blockIdx.y;
    int f = blockIdx.x*768 + threadIdx.x;
    int beg = g_rowptr[n], end = g_rowptr[n+1];
    float sw = g_selfw[n];
    const float* r = in + n*ROWLEN;
    float a0 = sw*r[f], a1 = sw*r[f+256], a2 = sw*r[f+512];
    for (int e = beg; e < end; e++) {
        int s = g_col[e]; float w = g_wval[e];
        const float* rs = in + s*ROWLEN;
        a0 += w*rs[f]; a1 += w*rs[f+256]; a2 += w*rs[f+512];
    }
    int o = n*ROWLEN + f;
    if (mode == 1) {
        out[o] = a0; out[o+256] = a1; out[o+512] = a2;
    } else {
        out[o]     = 2.f*a0 - g_x0[o];
        out[o+256] = 2.f*a1 - g_x0[o+256];
        out[o+512] = 2.f*a2 - g_x0[o+512];
    }
}

// ---------------- Chebyshev contraction: out = relu([x0|y1|z2] @ Wcheb + b) ----------------
// M = 192000, K = 96, N = 64.  W_cheb [3][32][64] is exactly the [96][64] concat layout.
__global__ void k_gemm(const float* __restrict__ wcheb, const float* __restrict__ bcheb) {
    extern __shared__ float sm[];
    float* As = sm;            // [64 rows][96 k]
    float* Ws = sm + 64*96;    // [96 k][64 f]
    int row0 = blockIdx.x * 64;
    int tid = threadIdx.x;
    for (int i = tid; i < 96*64; i += 256) Ws[i] = wcheb[i];
    for (int i = tid; i < 64*96; i += 256) {
        int r = i / 96, c = i - r*96;
        const float* src = (c < 32) ? g_x0 : ((c < 64) ? g_y1 : g_z2);
        As[i] = src[(row0 + r)*32 + (c & 31)];
    }
    __syncthreads();
    int tx = tid & 15, ty = tid >> 4;   // 16x16 thread grid, 4x4 per thread
    float acc[4][4] = {};
    #pragma unroll 8
    for (int c = 0; c < 96; c++) {
        float4 w4 = reinterpret_cast<float4*>(Ws)[c*16 + tx];
        #pragma unroll
        for (int k = 0; k < 4; k++) {
            float av = As[(ty*4 + k)*96 + c];
            acc[k][0] += av*w4.x; acc[k][1] += av*w4.y;
            acc[k][2] += av*w4.z; acc[k][3] += av*w4.w;
        }
    }
    const float4 bb4 = reinterpret_cast<const float4*>(bcheb)[tx];
    #pragma unroll
    for (int k = 0; k < 4; k++) {
        int row = row0 + ty*4 + k;
        float4 o;
        o.x = fmaxf(acc[k][0] + bb4.x, 0.f);
        o.y = fmaxf(acc[k][1] + bb4.y, 0.f);
        o.z = fmaxf(acc[k][2] + bb4.z, 0.f);
        o.w = fmaxf(acc[k][3] + bb4.w, 0.f);
        reinterpret_cast<float4*>(g_out + row*64)[tx] = o;
    }
}

// ---------------- fused temporal conv + residual + relu + LayerNorm + output ----------------
// block = (b, 8 nodes), 512 threads: thread = (f = tid&63, ng = tid>>6)
__global__ void k_epi(const float* __restrict__ X,  const float* __restrict__ tw,
                      const float* __restrict__ tb, const float* __restrict__ rw,
                      const float* __restrict__ rb, const float* __restrict__ lg,
                      const float* __restrict__ lb, float* __restrict__ O) {
    extern __shared__ float sm[];
    float* tw_s = sm;                 // [f][192] padded to 193  (12352)
    float* rw_s = tw_s + 64*193;      // [f][32] padded to 33    (2112)
    float* tb_s = rw_s + 2112;        // 64
    float* rb_s = tb_s + 64;
    float* lg_s = rb_s + 64;
    float* lb_s = lg_s + 64;
    float* xcT  = lb_s + 64;          // [ng][fc*12 + t]  6144 (aliased as zb later)
    float* xs   = xcT + 6144;         // [ng][c*12 + t]   3072
    float* mu_s = xs + 3072;          // 96
    float* rs_s = mu_s + 96;          // 96

    int b  = blockIdx.y;
    int n0 = blockIdx.x * 8;
    int tid = threadIdx.x;

    for (int i = tid; i < 64*192; i += 512) { int fq = i/192, r = i - fq*192; tw_s[fq*193 + r] = tw[i]; }
    for (int i = tid; i < 64*32;  i += 512) { int fq = i/32,  c = i - fq*32;  rw_s[fq*33  + c] = rw[i]; }
    if (tid < 64) { tb_s[tid] = tb[tid]; rb_s[tid] = rb[tid]; lg_s[tid] = lg[tid]; lb_s[tid] = lb[tid]; }
    // Xc[b,n,fc,t] = g_out[n*96 + b*12 + t][fc] -> transpose to [fc][t] for float4 t-loads
    for (int i = tid; i < 8*768; i += 512) {
        int ng = i/768, j = i - ng*768;
        int t = j >> 6, fc = j & 63;
        xcT[ng*768 + fc*12 + t] = g_out[((n0 + ng)*TBm + b*TT)*64 + j];
    }
    for (int i = tid; i < 8*384; i += 512) {
        int ng = i/384, j = i - ng*384;
        xs[i] = X[((b*NN + (n0 + ng))*CIN)*TT + j];
    }
    __syncthreads();

    int f = tid & 63, ng = tid >> 6;
    float acc[12];
    {
        float init = tb_s[f] + rb_s[f];
        #pragma unroll
        for (int t = 0; t < 12; t++) acc[t] = init;
    }
    // temporal 1x3 conv over t (pad 1): h[t] += xc[fc, t-1+j] * tw[f,fc,j]
    const float* xc = xcT + ng*768;
    #pragma unroll 4
    for (int fc = 0; fc < 64; fc++) {
        float w0 = tw_s[f*193 + fc*3 + 0];
        float w1 = tw_s[f*193 + fc*3 + 1];
        float w2 = tw_s[f*193 + fc*3 + 2];
        float4 v0 = *reinterpret_cast<const float4*>(xc + fc*12 + 0);
        float4 v1 = *reinterpret_cast<const float4*>(xc + fc*12 + 4);
        float4 v2 = *reinterpret_cast<const float4*>(xc + fc*12 + 8);
        float xv[12] = {v0.x,v0.y,v0.z,v0.w, v1.x,v1.y,v1.z,v1.w, v2.x,v2.y,v2.z,v2.w};
        #pragma unroll
        for (int t = 0; t < 12; t++) {
            float v = xv[t];
            if (t < 11) acc[t+1] += v*w0;
            acc[t] += v*w1;
            if (t > 0)  acc[t-1] += v*w2;
        }
    }
    // 1x1 residual conv on raw X
    const float* xrow = xs + ng*384;
    #pragma unroll 4
    for (int c = 0; c < 32; c++) {
        float rwv = rw_s[f*33 + c];
        float4 v0 = *reinterpret_cast<const float4*>(xrow + c*12 + 0);
        float4 v1 = *reinterpret_cast<const float4*>(xrow + c*12 + 4);
        float4 v2 = *reinterpret_cast<const float4*>(xrow + c*12 + 8);
        float xv[12] = {v0.x,v0.y,v0.z,v0.w, v1.x,v1.y,v1.z,v1.w, v2.x,v2.y,v2.z,v2.w};
        #pragma unroll
        for (int t = 0; t < 12; t++) acc[t] += xv[t]*rwv;
    }
    __syncthreads();           // done reading xcT -> safe to alias as zb
    float* zb = xcT;
    #pragma unroll
    for (int t = 0; t < 12; t++)
        zb[(ng*12 + t)*64 + f] = fmaxf(acc[t], 0.f);
    __syncthreads();

    // LayerNorm over f per (ng, t): 16 warps x 6 rows = 96 rows
    int wid = tid >> 5, lane = tid & 31;
    for (int k = 0; k < 6; k++) {
        int row = wid*6 + k;
        float v1 = zb[row*64 + lane];
        float v2 = zb[row*64 + 32 + lane];
        float s = v1 + v2, q = v1*v1 + v2*v2;
        #pragma unroll
        for (int o = 16; o > 0; o >>= 1) {
            s += __shfl_xor_sync(0xffffffffu, s, o);
            q += __shfl_xor_sync(0xffffffffu, q, o);
        }
        if (lane == 0) {
            float mu  = s * (1.f/64.f);
            float var = q * (1.f/64.f) - mu*mu;
            mu_s[row] = mu;
            rs_s[row] = rsqrtf(var + 1e-5f);
        }
    }
    __syncthreads();

    // output O[b, n, f, t] — coalesced 768-float block per node
    int obase = ((b*NN + (n0 + ng))*64)*12;
    for (int k = 0; k < 12; k++) {
        int i = k*64 + f;                 // 0..767
        int fo = i / 12, to = i - fo*12;
        float z  = zb[(ng*12 + to)*64 + fo];
        float mu = mu_s[ng*12 + to], rs = rs_s[ng*12 + to];
        O[obase + i] = (z - mu)*rs*lg_s[fo] + lb_s[fo];
    }
}

// ---------------- launch ----------------
extern "C" void kernel_launch(void* const* d_in, const int* in_sizes, int n_in,
                              void* d_out, int out_size) {
    const float* X     = (const float*)d_in[0];
    const int*   ei    = (const int*)  d_in[1];
    const float* ew    = (const float*)d_in[2];
    const float* lmax  = (const float*)d_in[3];
    const float* wcheb = (const float*)d_in[4];
    const float* bcheb = (const float*)d_in[5];
    const float* tw    = (const float*)d_in[6];
    const float* tb    = (const float*)d_in[7];
    const float* rw    = (const float*)d_in[8];
    const float* rb    = (const float*)d_in[9];
    const float* lng   = (const float*)d_in[10];
    const float* lnb   = (const float*)d_in[11];
    float* O = (float*)d_out;

    cudaFuncSetAttribute(k_gemm, cudaFuncAttributeMaxDynamicSharedMemorySize, 49152);
    cudaFuncSetAttribute(k_epi,  cudaFuncAttributeMaxDynamicSharedMemorySize, 96512);

    k_zero   <<<8,   256>>>();
    k_count  <<<125, 256>>>(ei, ew);
    k_scan   <<<1,  1024>>>(lmax);
    k_scatter<<<125, 256>>>(ei, ew, lmax);
    k_x0     <<<2000,256>>>(X);
    k_prop   <<<dim3(4,2000),256>>>(1);
    k_prop   <<<dim3(4,2000),256>>>(2);
    k_gemm   <<<3000,256,49152>>>(wcheb, bcheb);
    k_epi    <<<dim3(250,8),512,96512>>>(X, tw, tb, rw, rb, lng, lnb, O);
}